// round 2
// baseline (speedup 1.0000x reference)
#include <cuda_runtime.h>

#define BB   8
#define CC   64
#define TT   192
#define FFR  128
#define LTm  192               // time view L
#define LFm  128               // freq view L
#define DTm  (CC*FFR)          // 8192
#define DFm  (CC*TT)           // 12288
#define NEL  (BB*CC*TT*FFR)    // 12,582,912
#define HH   4

// ---------------- scratch (device globals; no allocations) ----------------
__device__ float g_XT[2][NEL];                  // transposed time-view X for s,t
__device__ float g_G[2][2][BB*LTm*LTm];         // [view][which] gram -> overwritten with logPs / Pt_row
__device__ float g_inv[2][2][BB*LTm];           // 1/max(norm,eps)
__device__ float g_mean[2][2][BB*LTm];          // row means of P
__device__ float g_ent[2][BB*LTm];              // entropy terms (t side)
__device__ float g_qk[2][2][BB*LTm*HH];         // q (sel=0), k (sel=1)
__device__ float g_alpha[2][BB*LTm*LTm];
__device__ float g_colsum[2][BB*LTm];
__device__ float g_part[2][256];

// ---------------- small helpers ----------------
__device__ __forceinline__ float warpSum(float v) {
#pragma unroll
    for (int o = 16; o; o >>= 1) v += __shfl_xor_sync(0xffffffffu, v, o);
    return v;
}
__device__ __forceinline__ float warpMax(float v) {
#pragma unroll
    for (int o = 16; o; o >>= 1) v = fmaxf(v, __shfl_xor_sync(0xffffffffu, v, o));
    return v;
}
__device__ __forceinline__ float blockSum(float v, float* sm) {
    v = warpSum(v);
    int w = threadIdx.x >> 5;
    __syncthreads();
    if ((threadIdx.x & 31) == 0) sm[w] = v;
    __syncthreads();
    float r = 0.f;
    int nw = (blockDim.x + 31) >> 5;
    for (int i = 0; i < nw; i++) r += sm[i];
    return r;
}
__device__ __forceinline__ float blockMax(float v, float* sm) {
    v = warpMax(v);
    int w = threadIdx.x >> 5;
    __syncthreads();
    if ((threadIdx.x & 31) == 0) sm[w] = v;
    __syncthreads();
    float r = -3.402823466e38f;
    int nw = (blockDim.x + 31) >> 5;
    for (int i = 0; i < nw; i++) r = fmaxf(r, sm[i]);
    return r;
}

union Cvt { unsigned long long u; float2 f; };

__device__ __forceinline__ void lds_v2u64(unsigned long long& x, unsigned long long& y, unsigned addr) {
    asm volatile("ld.shared.v2.u64 {%0,%1}, [%2];" : "=l"(x), "=l"(y) : "r"(addr));
}
__device__ __forceinline__ void fma2(unsigned long long& d, unsigned long long a, unsigned long long b) {
    asm volatile("fma.rn.f32x2 %0, %1, %2, %0;" : "+l"(d) : "l"(a), "l"(b));
}

// ---------------- 1) transpose feat (B,C,T,Fr) -> (B,C,Fr,T), both tensors ----------------
__global__ void transpose_kernel(const float* __restrict__ fs, const float* __restrict__ ft) {
    __shared__ float tile[32][33];
    int z = blockIdx.z;
    int which = z >> 9;            // 0..511 -> fs, 512..1023 -> ft
    int bc = z & 511;
    const float* in = which ? ft : fs;
    int t0 = blockIdx.x * 32, f0 = blockIdx.y * 32;
    const float* src = in + (size_t)bc * TT * FFR;
    float* out = g_XT[which] + (size_t)bc * TT * FFR;
    int tx = threadIdx.x, ty = threadIdx.y;
#pragma unroll
    for (int i = 0; i < 32; i += 8)
        tile[ty + i][tx] = src[(size_t)(t0 + ty + i) * FFR + f0 + tx];
    __syncthreads();
#pragma unroll
    for (int i = 0; i < 32; i += 8)
        out[(size_t)(f0 + ty + i) * TT + t0 + tx] = tile[tx][ty + i];
}

// ---------------- 2) fused SYRK: G = X X^T (both views, one wave) ----------------
// X[row, k] at base + k*L + row (unit row stride). 64x64 output tile per block,
// triangular tile pairs only (mirror written). Inner math = packed fp32x2 FMA.
__global__ void __launch_bounds__(256, 1) gram_kernel(const float* __restrict__ fs,
                                                      const float* __restrict__ ft) {
    int idx = blockIdx.x;
    int view, p, b, which, L, D, nt;
    if (idx < 96) { view = 0; L = LTm; D = DTm; nt = 3; p = idx % 6; b = (idx / 6) & 7; which = idx / 48; }
    else { int r = idx - 96; view = 1; L = LFm; D = DFm; nt = 2; p = r % 3; b = (r / 3) & 7; which = r / 24; }

    int pi = 0, rem = p, rl = nt;
    while (rem >= rl) { rem -= rl; pi++; rl--; }
    int pj = pi + rem;
    int i0 = pi * 64, j0 = pj * 64;

    const float* X;
    if (view == 0) X = g_XT[which];
    else           X = which ? ft : fs;
    X += (size_t)b * L * D;
    float* G = g_G[view][which] + (size_t)b * L * L;

    __shared__ __align__(16) float sA[32 * 128];   // duplicated: (v,v) per element, k-major
    __shared__ __align__(16) float sB[32 * 64];    // k-major

    int tid = threadIdx.x;
    int lr = tid & 63, lk = tid >> 6;              // loader mapping: row fast (coalesced)
    const float* pa = X + i0 + lr;
    const float* pb = X + j0 + lr;
    int nch = D >> 5;

    float ra[8], rb[8];
#pragma unroll
    for (int q = 0; q < 8; q++) {
        int kk = lk * 8 + q;
        ra[q] = pa[(size_t)kk * L];
        rb[q] = pb[(size_t)kk * L];
    }

    int tx = tid & 15, ty = tid >> 4;
    unsigned long long acc[4][2];
#pragma unroll
    for (int u = 0; u < 4; u++) { acc[u][0] = 0ull; acc[u][1] = 0ull; }

    unsigned sAb = (unsigned)__cvta_generic_to_shared(sA);
    unsigned sBb = (unsigned)__cvta_generic_to_shared(sB);
    unsigned aBase = sAb + (unsigned)ty * 32;
    unsigned bBase = sBb + (unsigned)tx * 16;

    for (int ch = 0; ; ch++) {
        __syncthreads();
#pragma unroll
        for (int q = 0; q < 8; q++) {
            int kk = lk * 8 + q;
            ((float2*)sA)[kk * 64 + lr] = make_float2(ra[q], ra[q]);
            sB[kk * 64 + lr] = rb[q];
        }
        __syncthreads();
        bool more = (ch + 1 < nch);
        if (more) {
            const float* pa2 = pa + (size_t)(ch + 1) * 32 * L;
            const float* pb2 = pb + (size_t)(ch + 1) * 32 * L;
#pragma unroll
            for (int q = 0; q < 8; q++) {
                int kk = lk * 8 + q;
                ra[q] = pa2[(size_t)kk * L];
                rb[q] = pb2[(size_t)kk * L];
            }
        }
#pragma unroll
        for (int kk = 0; kk < 32; kk++) {
            unsigned long long a0, a1, a2, a3, b01, b23;
            lds_v2u64(a0, a1, aBase + kk * 512);
            lds_v2u64(a2, a3, aBase + kk * 512 + 16);
            lds_v2u64(b01, b23, bBase + kk * 256);
            fma2(acc[0][0], a0, b01); fma2(acc[0][1], a0, b23);
            fma2(acc[1][0], a1, b01); fma2(acc[1][1], a1, b23);
            fma2(acc[2][0], a2, b01); fma2(acc[2][1], a2, b23);
            fma2(acc[3][0], a3, b01); fma2(acc[3][1], a3, b23);
        }
        if (!more) break;
    }

#pragma unroll
    for (int u = 0; u < 4; u++) {
        Cvt c0, c1; c0.u = acc[u][0]; c1.u = acc[u][1];
        int i = i0 + ty * 4 + u;
        float4 v4 = make_float4(c0.f.x, c0.f.y, c1.f.x, c1.f.y);
        *(float4*)&G[(size_t)i * L + j0 + tx * 4] = v4;
        if (pi != pj) {
            int j = j0 + tx * 4;
            G[(size_t)(j + 0) * L + i] = v4.x;
            G[(size_t)(j + 1) * L + i] = v4.y;
            G[(size_t)(j + 2) * L + i] = v4.z;
            G[(size_t)(j + 3) * L + i] = v4.w;
        }
    }
}

// ---------------- 3) inverse norms from gram diagonal ----------------
__global__ void norms_kernel(int view, int L) {
    int b = blockIdx.x, which = blockIdx.y, l = threadIdx.x;
    float g = g_G[view][which][(size_t)b * L * L + (size_t)l * L + l];
    g_inv[view][which][b * L + l] = 1.0f / fmaxf(sqrtf(g), 1e-8f);
}

// ---------------- 4) per-row: P, rowmean, softmax(+eps), log / entropy (in place) ----------------
__global__ void rowproc_kernel(int view, int L) {
    __shared__ float red[8];
    int l = blockIdx.x, b = blockIdx.y, which = blockIdx.z;
    int m = threadIdx.x;
    float* G = g_G[view][which] + (size_t)b * L * L + (size_t)l * L;
    float invl = g_inv[view][which][b * L + l];
    float invm = g_inv[view][which][b * L + m];
    float pv = 0.5f * (G[m] * invl * invm + 1.0f);

    float s = blockSum(pv, red);
    if (m == 0) g_mean[view][which][b * L + l] = s / (float)L;

    float mx = blockMax(pv, red);
    float e = expf(pv - mx);
    float Z = blockSum(e, red);
    float sp = e / Z + 1e-8f;                    // P_row = softmax + EPS

    if (which == 0) {
        G[m] = logf(sp + 1e-8f);                 // logPs = log(P_row + EPS)  (EPS twice, matches ref)
    } else {
        G[m] = sp;                               // Pt_row
        float ent = blockSum(sp * logf(sp + 1e-8f), red);   // sum Pt*log(Pt+EPS)
        if (m == 0) g_ent[view][b * L + l] = ent;
    }
}

// ---------------- 5) tiny MLP (Linear(1,H)+ReLU+LayerNorm) ----------------
__global__ void mlp_kernel(int view, int L,
                           const float* __restrict__ Wq, const float* __restrict__ bq,
                           const float* __restrict__ gq, const float* __restrict__ Bq,
                           const float* __restrict__ Wk, const float* __restrict__ bk,
                           const float* __restrict__ gk, const float* __restrict__ Bk) {
    int b = blockIdx.x, sel = blockIdx.y;       // 0: q from s-means, 1: k from t-means
    int l = threadIdx.x;
    const float* W  = sel ? Wk : Wq;
    const float* bi = sel ? bk : bq;
    const float* gg = sel ? gk : gq;
    const float* be = sel ? Bk : Bq;
    float x = g_mean[view][sel][b * L + l];
    float h[HH]; float mu = 0.f;
#pragma unroll
    for (int j = 0; j < HH; j++) { h[j] = fmaxf(W[j] * x + bi[j], 0.f); mu += h[j]; }
    mu *= (1.0f / HH);
    float var = 0.f;
#pragma unroll
    for (int j = 0; j < HH; j++) { float d = h[j] - mu; var += d * d; }
    var *= (1.0f / HH);
    float inv = rsqrtf(var + 1e-5f);
#pragma unroll
    for (int j = 0; j < HH; j++)
        g_qk[view][sel][((size_t)b * L + l) * HH + j] = gg[j] * (h[j] - mu) * inv + be[j];
}

// ---------------- 6) alpha = softmax(q k^T / sqrt(H+eps)) ----------------
__global__ void alpha_kernel(int view, int L) {
    __shared__ float kb[LTm * HH];
    __shared__ float red[8];
    int s = blockIdx.x, b = blockIdx.y;
    int t = threadIdx.x;
    for (int i = t; i < L * HH; i += blockDim.x)
        kb[i] = g_qk[view][1][(size_t)b * L * HH + i];
    float q0 = g_qk[view][0][((size_t)b * L + s) * HH + 0];
    float q1 = g_qk[view][0][((size_t)b * L + s) * HH + 1];
    float q2 = g_qk[view][0][((size_t)b * L + s) * HH + 2];
    float q3 = g_qk[view][0][((size_t)b * L + s) * HH + 3];
    __syncthreads();
    float invScale = rsqrtf(4.0f + 1e-8f);
    float a = (q0 * kb[t * 4 + 0] + q1 * kb[t * 4 + 1] + q2 * kb[t * 4 + 2] + q3 * kb[t * 4 + 3]) * invScale;
    float mx = blockMax(a, red);
    float e = expf(a - mx);
    float Z = blockSum(e, red);
    g_alpha[view][(size_t)b * L * L + (size_t)s * L + t] = e / Z;
}

// ---------------- 7) column sums of alpha ----------------
__global__ void colsum_kernel(int view, int L) {
    int b = blockIdx.x, t = threadIdx.x;
    const float* al = g_alpha[view] + (size_t)b * L * L;
    float s = 0.f;
    for (int ss = 0; ss < L; ss++) s += al[(size_t)ss * L + t];
    g_colsum[view][b * L + t] = s;
}

// ---------------- 8) term2 partials: sum_{s,k} logPs[s,k] * (alpha @ Pt_row)[s,k] ----------------
__global__ void part_kernel(int view, int L) {
    __shared__ float sal[8][LTm];
    __shared__ float red[8];
    int b = blockIdx.y, s0 = blockIdx.x * 8;
    const float* logPs = g_G[view][0] + (size_t)b * L * L;
    const float* Pt    = g_G[view][1] + (size_t)b * L * L;
    const float* al    = g_alpha[view] + (size_t)b * L * L;
    int k = threadIdx.x;
#pragma unroll
    for (int i = 0; i < 8; i++) sal[i][k] = al[(size_t)(s0 + i) * L + k];
    __syncthreads();
    float m[8];
#pragma unroll
    for (int i = 0; i < 8; i++) m[i] = 0.f;
    for (int t = 0; t < L; t++) {
        float pv = Pt[(size_t)t * L + k];
#pragma unroll
        for (int i = 0; i < 8; i++) m[i] += sal[i][t] * pv;
    }
    float acc = 0.f;
#pragma unroll
    for (int i = 0; i < 8; i++) acc += m[i] * logPs[(size_t)(s0 + i) * L + k];
    float tot = blockSum(acc, red);
    if (k == 0) g_part[view][blockIdx.y * gridDim.x + blockIdx.x] = tot;
}

// ---------------- 9) final deterministic reduction ----------------
__global__ void final_kernel(float* out) {
    __shared__ float red[8];
    int tid = threadIdx.x;
    float t2T = 0.f; for (int i = tid; i < (LTm / 8) * BB; i += 256) t2T += g_part[0][i];
    t2T = blockSum(t2T, red);
    float t2F = 0.f; for (int i = tid; i < (LFm / 8) * BB; i += 256) t2F += g_part[1][i];
    t2F = blockSum(t2F, red);
    float t1T = 0.f; for (int i = tid; i < BB * LTm; i += 256) t1T += g_ent[0][i] * g_colsum[0][i];
    t1T = blockSum(t1T, red);
    float t1F = 0.f; for (int i = tid; i < BB * LFm; i += 256) t1F += g_ent[1][i] * g_colsum[1][i];
    t1F = blockSum(t1F, red);
    if (tid == 0) {
        float lt = (t1T - t2T) / ((float)BB * LTm * LTm + 1e-8f);
        float lf = (t1F - t2F) / ((float)BB * LFm * LFm + 1e-8f);
        out[0] = lt + lf;
    }
}

// ---------------- launch ----------------
extern "C" void kernel_launch(void* const* d_in, const int* in_sizes, int n_in,
                              void* d_out, int out_size) {
    const float* fs  = (const float*)d_in[0];
    const float* ft  = (const float*)d_in[1];
    const float* WqT = (const float*)d_in[2];
    const float* bqT = (const float*)d_in[3];
    const float* gqT = (const float*)d_in[4];
    const float* BqT = (const float*)d_in[5];
    const float* WkT = (const float*)d_in[6];
    const float* bkT = (const float*)d_in[7];
    const float* gkT = (const float*)d_in[8];
    const float* BkT = (const float*)d_in[9];
    const float* WqF = (const float*)d_in[10];
    const float* bqF = (const float*)d_in[11];
    const float* gqF = (const float*)d_in[12];
    const float* BqF = (const float*)d_in[13];
    const float* WkF = (const float*)d_in[14];
    const float* bkF = (const float*)d_in[15];
    const float* gkF = (const float*)d_in[16];
    const float* BkF = (const float*)d_in[17];
    float* out = (float*)d_out;

    transpose_kernel<<<dim3(TT / 32, FFR / 32, BB * CC * 2), dim3(32, 8)>>>(fs, ft);

    gram_kernel<<<144, 256>>>(fs, ft);

    norms_kernel<<<dim3(BB, 2), LTm>>>(0, LTm);
    norms_kernel<<<dim3(BB, 2), LFm>>>(1, LFm);

    rowproc_kernel<<<dim3(LTm, BB, 2), LTm>>>(0, LTm);
    rowproc_kernel<<<dim3(LFm, BB, 2), LFm>>>(1, LFm);

    mlp_kernel<<<dim3(BB, 2), LTm>>>(0, LTm, WqT, bqT, gqT, BqT, WkT, bkT, gkT, BkT);
    mlp_kernel<<<dim3(BB, 2), LFm>>>(1, LFm, WqF, bqF, gqF, BqF, WkF, bkF, gkF, BkF);

    alpha_kernel<<<dim3(LTm, BB), LTm>>>(0, LTm);
    alpha_kernel<<<dim3(LFm, BB), LFm>>>(1, LFm);

    colsum_kernel<<<BB, LTm>>>(0, LTm);
    colsum_kernel<<<BB, LFm>>>(1, LFm);

    part_kernel<<<dim3(LTm / 8, BB), LTm>>>(0, LTm);
    part_kernel<<<dim3(LFm / 8, BB), LFm>>>(1, LFm);

    final_kernel<<<1, 256>>>(out);
}